// round 3
// baseline (speedup 1.0000x reference)
#include <cuda_runtime.h>
#include <math.h>

#define PI_F 3.14159265358979323846f

__device__ float g_coef[256 * 6];

__global__ void prep_kernel(const float* __restrict__ theta, int B,
                            float sW, float sH) {
    int i = blockIdx.x * blockDim.x + threadIdx.x;
    if (i >= B * 6) return;
    int rc = i % 6;
    int r = rc / 3;
    const float m1[6] = {1.0f,  PI_F,        0.2f,  PI_F,        1.0f, 0.2f};
    const float m2[6] = {0.5f, -PI_F * 0.5f, -0.1f, -PI_F * 0.5f, 0.5f, -0.1f};
    float v = fmaf(theta[i], m1[rc], m2[rc]);
    g_coef[i] = v * (r == 0 ? sW : sH);
}

template <int PPT>
__global__ __launch_bounds__(256, 4)
void stn_kernel(const float* __restrict__ img, float* __restrict__ out,
                int H, int W, float inv) {
    const int b = blockIdx.z;
    const int h = blockIdx.y * blockDim.y + threadIdx.y;
    const int wbase = (blockIdx.x * blockDim.x + threadIdx.x) * PPT;
    if (h >= H || wbase >= W) return;

    const float c0 = g_coef[b * 6 + 0];
    const float c1 = g_coef[b * 6 + 1];
    const float c2 = g_coef[b * 6 + 2];
    const float c3 = g_coef[b * 6 + 3];
    const float c4 = g_coef[b * 6 + 4];
    const float c5 = g_coef[b * 6 + 5];

    const float yn = (float)h * inv;
    const float bx = fmaf(c1, yn, c2);   // xs = c0*xn + bx
    const float by = fmaf(c4, yn, c5);   // ys = c3*xn + by

    const float Wm1 = (float)(W - 1);
    const float Hm1 = (float)(H - 1);
    const float fw = (float)wbase;

    const float* __restrict__ imgb = img + (size_t)b * H * W;

    // Phase 1: coordinates, predicates, indices, weights for all PPT pixels.
    bool  inb[PPT];
    int   idx[PPT];
    float wx0[PPT], wx1[PPT], wy0[PPT], wy1[PPT];
#pragma unroll
    for (int p = 0; p < PPT; p++) {
        const float xn = (fw + (float)p) * inv;
        const float xs = fmaf(c0, xn, bx);
        const float ys = fmaf(c3, xn, by);

        // Reference: clamp-collapse (xs<0 || xs>=W-1, same for y) => exact 0.
        const bool ok = (xs >= 0.0f) && (xs < Wm1) && (ys >= 0.0f) && (ys < Hm1);
        inb[p] = ok;

        const int x0 = (int)xs;   // trunc == floor for xs>=0; garbage OK if !ok
        const int y0 = (int)ys;
        const float x0f = (float)x0;
        const float y0f = (float)y0;
        wx0[p] = xs - x0f;             // toward x1
        wx1[p] = (x0f + 1.0f) - xs;    // toward x0
        wy0[p] = ys - y0f;
        wy1[p] = (y0f + 1.0f) - ys;

        idx[p] = ok ? (y0 * W + x0) : 0;   // safe gather address when OOB
    }

    // Phase 2: issue all gathers back-to-back (no branches => high MLP).
    float Ia[PPT], Ib[PPT], Ic[PPT], Id[PPT];
#pragma unroll
    for (int p = 0; p < PPT; p++) {
        Ia[p] = __ldg(imgb + idx[p]);
        Ic[p] = __ldg(imgb + idx[p] + 1);
        Ib[p] = __ldg(imgb + idx[p] + W);
        Id[p] = __ldg(imgb + idx[p] + W + 1);
    }

    // Phase 3: combine + select.
    float res[PPT];
#pragma unroll
    for (int p = 0; p < PPT; p++) {
        const float v = wy1[p] * fmaf(wx1[p], Ia[p], wx0[p] * Ic[p]) +
                        wy0[p] * fmaf(wx1[p], Ib[p], wx0[p] * Id[p]);
        res[p] = inb[p] ? v : 0.0f;
    }

    float* __restrict__ op = out + (size_t)b * H * W + (size_t)h * W + wbase;
#pragma unroll
    for (int v = 0; v < PPT / 4; v++) {
        __stcs(reinterpret_cast<float4*>(op) + v,
               make_float4(res[v * 4 + 0], res[v * 4 + 1],
                           res[v * 4 + 2], res[v * 4 + 3]));
    }
}

extern "C" void kernel_launch(void* const* d_in, const int* in_sizes, int n_in,
                              void* d_out, int out_size) {
    const float* img   = (const float*)d_in[0];
    const float* theta = (const float*)d_in[1];

    const int B = in_sizes[1] / 6;
    const long long hw = (long long)in_sizes[0] / B;
    const int W = (int)(sqrt((double)hw) + 0.5);
    const int H = (int)(hw / W);

    prep_kernel<<<(B * 6 + 127) / 128, 128>>>(theta, B, (float)(W - 1), (float)(H - 1));

    constexpr int PPT = 8;
    dim3 blk(32, 8, 1);
    dim3 grd((W + 32 * PPT - 1) / (32 * PPT), (H + 7) / 8, B);
    stn_kernel<PPT><<<grd, blk>>>(img, (float*)d_out, H, W, 1.0f / (float)(W - 1));
}

// round 4
// speedup vs baseline: 1.8599x; 1.8599x over previous
#include <cuda_runtime.h>
#include <math.h>

#define PI_F 3.14159265358979323846f

__device__ float g_coef[256 * 6];

__global__ void prep_kernel(const float* __restrict__ theta, int B,
                            float sW, float sH) {
    int i = blockIdx.x * blockDim.x + threadIdx.x;
    if (i >= B * 6) return;
    int rc = i % 6;
    int r = rc / 3;
    const float m1[6] = {1.0f,  PI_F,        0.2f,  PI_F,        1.0f, 0.2f};
    const float m2[6] = {0.5f, -PI_F * 0.5f, -0.1f, -PI_F * 0.5f, 0.5f, -0.1f};
    float v = fmaf(theta[i], m1[rc], m2[rc]);
    g_coef[i] = v * (r == 0 ? sW : sH);
}

template <int PPT>
__global__ __launch_bounds__(256, 5)
void stn_kernel(const float* __restrict__ img, float* __restrict__ out,
                int H, int W, float inv) {
    const int b = blockIdx.z;
    const int h = blockIdx.y * blockDim.y + threadIdx.y;
    const int wbase = (blockIdx.x * blockDim.x + threadIdx.x) * PPT;
    if (h >= H || wbase >= W) return;

    const float c0 = g_coef[b * 6 + 0];
    const float c1 = g_coef[b * 6 + 1];
    const float c2 = g_coef[b * 6 + 2];
    const float c3 = g_coef[b * 6 + 3];
    const float c4 = g_coef[b * 6 + 4];
    const float c5 = g_coef[b * 6 + 5];

    const float yn = (float)h * inv;
    const float bx = fmaf(c1, yn, c2);   // xs = c0*xn + bx
    const float by = fmaf(c4, yn, c5);   // ys = c3*xn + by

    const float Wm1 = (float)(W - 1);
    const float Hm1 = (float)(H - 1);
    const float fw = (float)wbase;

    const float* __restrict__ imgb = img + (size_t)b * H * W;
    float* __restrict__ op = out + (size_t)b * H * W + (size_t)h * W + wbase;

    // Strip endpoint coords (xs/ys are linear in p => interval classification).
    const float xnA = fw * inv;
    const float xnB = (fw + (float)(PPT - 1)) * inv;
    const float xsA = fmaf(c0, xnA, bx), xsB = fmaf(c0, xnB, bx);
    const float ysA = fmaf(c3, xnA, by), ysB = fmaf(c3, xnB, by);

    const bool allin =
        (xsA >= 0.0f) & (xsB >= 0.0f) & (xsA < Wm1) & (xsB < Wm1) &
        (ysA >= 0.0f) & (ysB >= 0.0f) & (ysA < Hm1) & (ysB < Hm1);
    const bool allout =
        ((xsA < 0.0f)   & (xsB < 0.0f))   | ((xsA >= Wm1) & (xsB >= Wm1)) |
        ((ysA < 0.0f)   & (ysB < 0.0f))   | ((ysA >= Hm1) & (ysB >= Hm1));

    if (allout) {
        const float4 z = make_float4(0.f, 0.f, 0.f, 0.f);
#pragma unroll
        for (int v = 0; v < PPT / 4; v++)
            __stcs(reinterpret_cast<float4*>(op) + v, z);
        return;
    }

    float res[PPT];

    if (allin) {
        // Branch-free interior path: 4-pixel stages, 16 gathers batched.
#pragma unroll
        for (int s = 0; s < PPT / 4; s++) {
            int   idx[4];
            float wx0[4], wx1[4], wy0[4], wy1[4];
#pragma unroll
            for (int i = 0; i < 4; i++) {
                const int p = s * 4 + i;
                const float xn = (fw + (float)p) * inv;
                const float xs = fmaf(c0, xn, bx);
                const float ys = fmaf(c3, xn, by);
                const int x0 = (int)xs;      // xs >= 0 guaranteed
                const int y0 = (int)ys;
                const float x0f = (float)x0;
                const float y0f = (float)y0;
                wx0[i] = xs - x0f;
                wx1[i] = (x0f + 1.0f) - xs;
                wy0[i] = ys - y0f;
                wy1[i] = (y0f + 1.0f) - ys;
                idx[i] = y0 * W + x0;
            }
            float Ia[4], Ib[4], Ic[4], Id[4];
#pragma unroll
            for (int i = 0; i < 4; i++) {
                Ia[i] = __ldg(imgb + idx[i]);
                Ic[i] = __ldg(imgb + idx[i] + 1);
                Ib[i] = __ldg(imgb + idx[i] + W);
                Id[i] = __ldg(imgb + idx[i] + W + 1);
            }
#pragma unroll
            for (int i = 0; i < 4; i++) {
                res[s * 4 + i] =
                    wy1[i] * fmaf(wx1[i], Ia[i], wx0[i] * Ic[i]) +
                    wy0[i] * fmaf(wx1[i], Ib[i], wx0[i] * Id[i]);
            }
        }
    } else {
        // Mixed strip (crosses a boundary): per-pixel branch, identical
        // predicate arithmetic to the interior test.
#pragma unroll
        for (int p = 0; p < PPT; p++) {
            const float xn = (fw + (float)p) * inv;
            const float xs = fmaf(c0, xn, bx);
            const float ys = fmaf(c3, xn, by);
            float r = 0.0f;
            if (xs >= 0.0f && xs < Wm1 && ys >= 0.0f && ys < Hm1) {
                const int x0 = (int)xs;
                const int y0 = (int)ys;
                const float x0f = (float)x0;
                const float y0f = (float)y0;
                const float fx0 = xs - x0f;
                const float fx1 = (x0f + 1.0f) - xs;
                const float fy0 = ys - y0f;
                const float fy1 = (y0f + 1.0f) - ys;
                const int idx = y0 * W + x0;
                const float Ia = __ldg(imgb + idx);
                const float Ic = __ldg(imgb + idx + 1);
                const float Ib = __ldg(imgb + idx + W);
                const float Id = __ldg(imgb + idx + W + 1);
                r = fy1 * fmaf(fx1, Ia, fx0 * Ic) +
                    fy0 * fmaf(fx1, Ib, fx0 * Id);
            }
            res[p] = r;
        }
    }

#pragma unroll
    for (int v = 0; v < PPT / 4; v++) {
        __stcs(reinterpret_cast<float4*>(op) + v,
               make_float4(res[v * 4 + 0], res[v * 4 + 1],
                           res[v * 4 + 2], res[v * 4 + 3]));
    }
}

extern "C" void kernel_launch(void* const* d_in, const int* in_sizes, int n_in,
                              void* d_out, int out_size) {
    const float* img   = (const float*)d_in[0];
    const float* theta = (const float*)d_in[1];

    const int B = in_sizes[1] / 6;
    const long long hw = (long long)in_sizes[0] / B;
    const int W = (int)(sqrt((double)hw) + 0.5);
    const int H = (int)(hw / W);

    prep_kernel<<<(B * 6 + 127) / 128, 128>>>(theta, B, (float)(W - 1), (float)(H - 1));

    constexpr int PPT = 8;
    dim3 blk(32, 8, 1);
    dim3 grd((W + 32 * PPT - 1) / (32 * PPT), (H + 7) / 8, B);
    stn_kernel<PPT><<<grd, blk>>>(img, (float*)d_out, H, W, 1.0f / (float)(W - 1));
}

// round 5
// speedup vs baseline: 2.0648x; 1.1102x over previous
#include <cuda_runtime.h>
#include <math.h>

#define PI_F 3.14159265358979323846f

__device__ float g_coef[256 * 6];

__global__ void prep_kernel(const float* __restrict__ theta, int B,
                            float sW, float sH) {
    int i = blockIdx.x * blockDim.x + threadIdx.x;
    if (i >= B * 6) return;
    int rc = i % 6;
    int r = rc / 3;
    const float m1[6] = {1.0f,  PI_F,        0.2f,  PI_F,        1.0f, 0.2f};
    const float m2[6] = {0.5f, -PI_F * 0.5f, -0.1f, -PI_F * 0.5f, 0.5f, -0.1f};
    float v = fmaf(theta[i], m1[rc], m2[rc]);
    g_coef[i] = v * (r == 0 ? sW : sH);
}

// Block covers a 32x32 output tile. Warp covers 32x4 (8 lanes in x * 4 in y),
// each thread computes 4 consecutive x pixels (one float4 store).
__global__ __launch_bounds__(256)
void stn_kernel(const float* __restrict__ img, float* __restrict__ out,
                int H, int W, float inv) {
    const int b = blockIdx.z;
    const int tx = threadIdx.x;          // 0..31
    const int ty = threadIdx.y;          // 0..7
    const int lx = tx & 7;               // lane x-group
    const int ly = tx >> 3;              // lane y within warp tile

    const int wpix = blockIdx.x * 32 + lx * 4;     // first of 4 x pixels
    const int hpix = blockIdx.y * 32 + ty * 4 + ly;
    if (hpix >= H || wpix >= W) return;

    const float c0 = g_coef[b * 6 + 0];
    const float c1 = g_coef[b * 6 + 1];
    const float c2 = g_coef[b * 6 + 2];
    const float c3 = g_coef[b * 6 + 3];
    const float c4 = g_coef[b * 6 + 4];
    const float c5 = g_coef[b * 6 + 5];

    const float yn = (float)hpix * inv;
    const float bx = fmaf(c1, yn, c2);   // xs = c0*xn + bx
    const float by = fmaf(c4, yn, c5);   // ys = c3*xn + by

    const float Wm1 = (float)(W - 1);
    const float Hm1 = (float)(H - 1);
    const float fw = (float)wpix;

    const float* __restrict__ imgb = img + (size_t)b * H * W;
    float* __restrict__ op = out + (size_t)b * H * W + (size_t)hpix * W + wpix;

    // Strip endpoints (xs/ys linear in p => interval classification).
    const float xnA = fw * inv;
    const float xnB = (fw + 3.0f) * inv;
    const float xsA = fmaf(c0, xnA, bx), xsB = fmaf(c0, xnB, bx);
    const float ysA = fmaf(c3, xnA, by), ysB = fmaf(c3, xnB, by);

    const bool allin =
        (xsA >= 0.0f) & (xsB >= 0.0f) & (xsA < Wm1) & (xsB < Wm1) &
        (ysA >= 0.0f) & (ysB >= 0.0f) & (ysA < Hm1) & (ysB < Hm1);
    const bool allout =
        ((xsA < 0.0f)  & (xsB < 0.0f))  | ((xsA >= Wm1) & (xsB >= Wm1)) |
        ((ysA < 0.0f)  & (ysB < 0.0f))  | ((ysA >= Hm1) & (ysB >= Hm1));

    if (allout) {
        __stcs(reinterpret_cast<float4*>(op), make_float4(0.f, 0.f, 0.f, 0.f));
        return;
    }

    float res[4];

    if (allin) {
        int   idx[4];
        float wx0[4], wx1[4], wy0[4], wy1[4];
#pragma unroll
        for (int i = 0; i < 4; i++) {
            const float xn = (fw + (float)i) * inv;
            const float xs = fmaf(c0, xn, bx);
            const float ys = fmaf(c3, xn, by);
            const int x0 = (int)xs;          // xs >= 0 guaranteed
            const int y0 = (int)ys;
            const float x0f = (float)x0;
            const float y0f = (float)y0;
            wx0[i] = xs - x0f;
            wx1[i] = (x0f + 1.0f) - xs;
            wy0[i] = ys - y0f;
            wy1[i] = (y0f + 1.0f) - ys;
            idx[i] = y0 * W + x0;
        }
        float Ia[4], Ib[4], Ic[4], Id[4];
#pragma unroll
        for (int i = 0; i < 4; i++) {
            Ia[i] = __ldg(imgb + idx[i]);
            Ic[i] = __ldg(imgb + idx[i] + 1);
            Ib[i] = __ldg(imgb + idx[i] + W);
            Id[i] = __ldg(imgb + idx[i] + W + 1);
        }
#pragma unroll
        for (int i = 0; i < 4; i++) {
            res[i] = wy1[i] * fmaf(wx1[i], Ia[i], wx0[i] * Ic[i]) +
                     wy0[i] * fmaf(wx1[i], Ib[i], wx0[i] * Id[i]);
        }
    } else {
        // Mixed strip: per-pixel branch, identical predicate arithmetic.
#pragma unroll
        for (int p = 0; p < 4; p++) {
            const float xn = (fw + (float)p) * inv;
            const float xs = fmaf(c0, xn, bx);
            const float ys = fmaf(c3, xn, by);
            float r = 0.0f;
            if (xs >= 0.0f && xs < Wm1 && ys >= 0.0f && ys < Hm1) {
                const int x0 = (int)xs;
                const int y0 = (int)ys;
                const float x0f = (float)x0;
                const float y0f = (float)y0;
                const float fx0 = xs - x0f;
                const float fx1 = (x0f + 1.0f) - xs;
                const float fy0 = ys - y0f;
                const float fy1 = (y0f + 1.0f) - ys;
                const int idx = y0 * W + x0;
                const float Ia = __ldg(imgb + idx);
                const float Ic = __ldg(imgb + idx + 1);
                const float Ib = __ldg(imgb + idx + W);
                const float Id = __ldg(imgb + idx + W + 1);
                r = fy1 * fmaf(fx1, Ia, fx0 * Ic) +
                    fy0 * fmaf(fx1, Ib, fx0 * Id);
            }
            res[p] = r;
        }
    }

    __stcs(reinterpret_cast<float4*>(op),
           make_float4(res[0], res[1], res[2], res[3]));
}

extern "C" void kernel_launch(void* const* d_in, const int* in_sizes, int n_in,
                              void* d_out, int out_size) {
    const float* img   = (const float*)d_in[0];
    const float* theta = (const float*)d_in[1];

    const int B = in_sizes[1] / 6;
    const long long hw = (long long)in_sizes[0] / B;
    const int W = (int)(sqrt((double)hw) + 0.5);
    const int H = (int)(hw / W);

    prep_kernel<<<(B * 6 + 127) / 128, 128>>>(theta, B, (float)(W - 1), (float)(H - 1));

    dim3 blk(32, 8, 1);
    dim3 grd((W + 31) / 32, (H + 31) / 32, B);
    stn_kernel<<<grd, blk>>>(img, (float*)d_out, H, W, 1.0f / (float)(W - 1));
}

// round 6
// speedup vs baseline: 2.2466x; 1.0880x over previous
#include <cuda_runtime.h>
#include <math.h>

#define PI_F 3.14159265358979323846f

__device__ float g_coef[256 * 6];

__global__ void prep_kernel(const float* __restrict__ theta, int B,
                            float sW, float sH) {
    int i = blockIdx.x * blockDim.x + threadIdx.x;
    if (i >= B * 6) return;
    int rc = i % 6;
    int r = rc / 3;
    const float m1[6] = {1.0f,  PI_F,        0.2f,  PI_F,        1.0f, 0.2f};
    const float m2[6] = {0.5f, -PI_F * 0.5f, -0.1f, -PI_F * 0.5f, 0.5f, -0.1f};
    float v = fmaf(theta[i], m1[rc], m2[rc]);
    g_coef[i] = v * (r == 0 ? sW : sH);
}

// Block covers a 32x64 output tile. Warp covers 32x8 (8 x-groups * 4 y-lanes,
// each thread owns a 4x2 pixel rectangle -> two float4 stores).
__global__ __launch_bounds__(256)
void stn_kernel(const float* __restrict__ img, float* __restrict__ out,
                int H, int W, float inv) {
    const int b = blockIdx.z;
    const int tx = threadIdx.x;          // 0..31
    const int ty = threadIdx.y;          // 0..7 (warp id)
    const int lx = tx & 7;               // x-group within warp
    const int ly = tx >> 3;              // y-lane within warp (0..3)

    const int wpix = blockIdx.x * 32 + lx * 4;          // 4 x pixels
    const int hpix = blockIdx.y * 64 + ty * 8 + ly * 2; // 2 y rows
    if (hpix >= H || wpix >= W) return;

    const float c0 = g_coef[b * 6 + 0];
    const float c1 = g_coef[b * 6 + 1];
    const float c2 = g_coef[b * 6 + 2];
    const float c3 = g_coef[b * 6 + 3];
    const float c4 = g_coef[b * 6 + 4];
    const float c5 = g_coef[b * 6 + 5];

    const float Wm1 = (float)(W - 1);
    const float Hm1 = (float)(H - 1);
    const float fw = (float)wpix;
    const float xnA = fw * inv;
    const float xnB = (fw + 3.0f) * inv;

    // Per-row bases (exact same arithmetic as the per-pixel reference path).
    float bxr[2], byr[2];
#pragma unroll
    for (int r = 0; r < 2; r++) {
        const float yn = (float)(hpix + r) * inv;
        bxr[r] = fmaf(c1, yn, c2);
        byr[r] = fmaf(c4, yn, c5);
    }

    // Rectangle classification via the 4 corners (xs/ys linear in w and h).
    bool allin = true, outL = true, outR = true, outT = true, outBo = true;
#pragma unroll
    for (int r = 0; r < 2; r++) {
        const float xA = fmaf(c0, xnA, bxr[r]), xB = fmaf(c0, xnB, bxr[r]);
        const float yA = fmaf(c3, xnA, byr[r]), yB = fmaf(c3, xnB, byr[r]);
        allin &= (xA >= 0.0f) & (xB >= 0.0f) & (xA < Wm1) & (xB < Wm1) &
                 (yA >= 0.0f) & (yB >= 0.0f) & (yA < Hm1) & (yB < Hm1);
        outL &= (xA < 0.0f) & (xB < 0.0f);
        outR &= (xA >= Wm1) & (xB >= Wm1);
        outT &= (yA < 0.0f) & (yB < 0.0f);
        outBo &= (yA >= Hm1) & (yB >= Hm1);
    }
    const bool allout = outL | outR | outT | outBo;

    const float* __restrict__ imgb = img + (size_t)b * H * W;
    float* __restrict__ op0 = out + (size_t)b * H * W + (size_t)hpix * W + wpix;

    if (allout) {
        const float4 z = make_float4(0.f, 0.f, 0.f, 0.f);
        __stcs(reinterpret_cast<float4*>(op0), z);
        __stcs(reinterpret_cast<float4*>(op0 + W), z);
        return;
    }

    if (allin) {
#pragma unroll
        for (int r = 0; r < 2; r++) {
            const float bx = bxr[r], by = byr[r];
            int   idx[4];
            float wx0[4], wx1[4], wy0[4], wy1[4];
#pragma unroll
            for (int i = 0; i < 4; i++) {
                const float xn = (fw + (float)i) * inv;
                const float xs = fmaf(c0, xn, bx);
                const float ys = fmaf(c3, xn, by);
                const int x0 = (int)xs;          // xs >= 0 guaranteed
                const int y0 = (int)ys;
                const float x0f = (float)x0;
                const float y0f = (float)y0;
                wx0[i] = xs - x0f;
                wx1[i] = (x0f + 1.0f) - xs;
                wy0[i] = ys - y0f;
                wy1[i] = (y0f + 1.0f) - ys;
                idx[i] = y0 * W + x0;
            }
            float Ia[4], Ib[4], Ic[4], Id[4];
#pragma unroll
            for (int i = 0; i < 4; i++) {
                Ia[i] = __ldg(imgb + idx[i]);
                Ic[i] = __ldg(imgb + idx[i] + 1);
                Ib[i] = __ldg(imgb + idx[i] + W);
                Id[i] = __ldg(imgb + idx[i] + W + 1);
            }
            float4 res;
            float* rp = &res.x;
#pragma unroll
            for (int i = 0; i < 4; i++) {
                rp[i] = wy1[i] * fmaf(wx1[i], Ia[i], wx0[i] * Ic[i]) +
                        wy0[i] * fmaf(wx1[i], Ib[i], wx0[i] * Id[i]);
            }
            __stcs(reinterpret_cast<float4*>(op0 + r * W), res);
        }
        return;
    }

    // Mixed rectangle: per-pixel branch, identical predicate arithmetic.
#pragma unroll
    for (int r = 0; r < 2; r++) {
        const float bx = bxr[r], by = byr[r];
        float res[4];
#pragma unroll
        for (int p = 0; p < 4; p++) {
            const float xn = (fw + (float)p) * inv;
            const float xs = fmaf(c0, xn, bx);
            const float ys = fmaf(c3, xn, by);
            float v = 0.0f;
            if (xs >= 0.0f && xs < Wm1 && ys >= 0.0f && ys < Hm1) {
                const int x0 = (int)xs;
                const int y0 = (int)ys;
                const float x0f = (float)x0;
                const float y0f = (float)y0;
                const float fx0 = xs - x0f;
                const float fx1 = (x0f + 1.0f) - xs;
                const float fy0 = ys - y0f;
                const float fy1 = (y0f + 1.0f) - ys;
                const int idx = y0 * W + x0;
                const float Ia = __ldg(imgb + idx);
                const float Ic = __ldg(imgb + idx + 1);
                const float Ib = __ldg(imgb + idx + W);
                const float Id = __ldg(imgb + idx + W + 1);
                v = fy1 * fmaf(fx1, Ia, fx0 * Ic) +
                    fy0 * fmaf(fx1, Ib, fx0 * Id);
            }
            res[p] = v;
        }
        __stcs(reinterpret_cast<float4*>(op0 + r * W),
               make_float4(res[0], res[1], res[2], res[3]));
    }
}

extern "C" void kernel_launch(void* const* d_in, const int* in_sizes, int n_in,
                              void* d_out, int out_size) {
    const float* img   = (const float*)d_in[0];
    const float* theta = (const float*)d_in[1];

    const int B = in_sizes[1] / 6;
    const long long hw = (long long)in_sizes[0] / B;
    const int W = (int)(sqrt((double)hw) + 0.5);
    const int H = (int)(hw / W);

    prep_kernel<<<(B * 6 + 127) / 128, 128>>>(theta, B, (float)(W - 1), (float)(H - 1));

    dim3 blk(32, 8, 1);
    dim3 grd((W + 31) / 32, (H + 63) / 64, B);
    stn_kernel<<<grd, blk>>>(img, (float*)d_out, H, W, 1.0f / (float)(W - 1));
}